// round 1
// baseline (speedup 1.0000x reference)
#include <cuda_runtime.h>

#define CH 32
#define SEGS 33
#define NMAX 50000

// ---- device-global scratch (no allocations allowed) ----
__device__ float g_bp_e[32], g_bp_a[32];
__device__ float g_trep_e[SEGS], g_trep_a[SEGS];
__device__ float g_A[SEGS * 1024];     // per-segment edge matrix, constant part (includes eb2)
__device__ float g_B[SEGS * 1024];     // per-segment edge matrix, t-slope part
__device__ float g_aA[SEGS * 32];      // per-segment angle vector, constant part
__device__ float g_aB[SEGS * 32];      // per-segment angle vector, slope part
__device__ float g_cnt[NMAX * SEGS];   // per (node, angle-segment) count
__device__ float g_ts[NMAX * SEGS];    // per (node, angle-segment) sum of t

// ---------------------------------------------------------------------------
// K1: breakpoints + sort + segment representatives (1 block, 64 threads)
// ---------------------------------------------------------------------------
__global__ void k_pre1(const float* __restrict__ eW1, const float* __restrict__ eb1,
                       const float* __restrict__ aW1, const float* __restrict__ ab1) {
    __shared__ float se[32], sa[32];
    int t = threadIdx.x;
    if (t < 32) {
        float w = eW1[t], b = eb1[t];
        float p = (w != 0.0f) ? (-b / w) : 2.0f;
        se[t] = fminf(fmaxf(p, -1.0f), 2.0f);   // t in [0,1): clamping is behavior-preserving
        float wa = aW1[t], ba = ab1[t];
        float pa = (wa != 0.0f) ? (-ba / wa) : 2.0f;
        sa[t] = fminf(fmaxf(pa, -1.0f), 2.0f);
    }
    __syncthreads();
    if (t == 0) {   // insertion sort, 32 elems
        for (int i = 1; i < 32; i++) {
            float v = se[i]; int j = i - 1;
            while (j >= 0 && se[j] > v) { se[j + 1] = se[j]; j--; }
            se[j + 1] = v;
        }
    }
    if (t == 1) {
        for (int i = 1; i < 32; i++) {
            float v = sa[i]; int j = i - 1;
            while (j >= 0 && sa[j] > v) { sa[j + 1] = sa[j]; j--; }
            sa[j + 1] = v;
        }
    }
    __syncthreads();
    if (t < 32) { g_bp_e[t] = se[t]; g_bp_a[t] = sa[t]; }
    if (t < SEGS) {
        float lo = (t == 0) ? -1.5f : se[t - 1];
        float hi = (t == 32) ? 2.5f : se[t];
        g_trep_e[t] = 0.5f * (lo + hi);
        float loa = (t == 0) ? -1.5f : sa[t - 1];
        float hia = (t == 32) ? 2.5f : sa[t];
        g_trep_a[t] = 0.5f * (loa + hia);
    }
}

// ---------------------------------------------------------------------------
// K2: build per-segment tables. Blocks 0..32: edge segment s. Block 33: angles.
// ---------------------------------------------------------------------------
__global__ void k_pre2(const float* __restrict__ eW1, const float* __restrict__ eb1,
                       const float* __restrict__ eW2, const float* __restrict__ eb2,
                       const float* __restrict__ aW1, const float* __restrict__ ab1,
                       const float* __restrict__ aW2, const float* __restrict__ ab2) {
    int s = blockIdx.x;
    if (s < SEGS) {
        __shared__ float w1[32], b1[32];
        if (threadIdx.x < 32) { w1[threadIdx.x] = eW1[threadIdx.x]; b1[threadIdx.x] = eb1[threadIdx.x]; }
        __syncthreads();
        float trep = g_trep_e[s];
        for (int io = threadIdx.x; io < 1024; io += blockDim.x) {
            float a = eb2[io], b = 0.0f;
            #pragma unroll
            for (int k = 0; k < 32; k++) {
                if (w1[k] * trep + b1[k] > 0.0f) {
                    float w2 = eW2[k * 1024 + io];
                    a = fmaf(b1[k], w2, a);
                    b = fmaf(w1[k], w2, b);
                }
            }
            g_A[s * 1024 + io] = a;
            g_B[s * 1024 + io] = b;
        }
    } else {
        for (int idx = threadIdx.x; idx < SEGS * 32; idx += blockDim.x) {
            int s2 = idx >> 5, o = idx & 31;
            float trep = g_trep_a[s2];
            float a = ab2[o], b = 0.0f;
            #pragma unroll
            for (int k = 0; k < 32; k++) {
                float w = aW1[k], bb = ab1[k];
                if (w * trep + bb > 0.0f) {
                    float w2 = aW2[k * 32 + o];
                    a = fmaf(bb, w2, a);
                    b = fmaf(w, w2, b);
                }
            }
            g_aA[idx] = a;
            g_aB[idx] = b;
        }
    }
}

// ---------------------------------------------------------------------------
// K3: zero output + (node,seg) accumulators
// ---------------------------------------------------------------------------
__global__ void k_init(float* __restrict__ out, int N) {
    int i = blockIdx.x * blockDim.x + threadIdx.x;
    if (i < N * 32) out[i] = 0.0f;
    if (i < N * SEGS) { g_cnt[i] = 0.0f; g_ts[i] = 0.0f; }
}

// ---------------------------------------------------------------------------
// K4: edge branch. One warp per edge, lane = output channel.
// ---------------------------------------------------------------------------
__global__ void k_edge(const float* __restrict__ x, const int* __restrict__ ei,
                       const float* __restrict__ ea, float* __restrict__ out, int E) {
    __shared__ float sbp[32];
    if (threadIdx.x < 32) sbp[threadIdx.x] = g_bp_e[threadIdx.x];
    __syncthreads();
    int e = (blockIdx.x * blockDim.x + threadIdx.x) >> 5;
    int lane = threadIdx.x & 31;
    if (e >= E) return;

    float t = __ldg(ea + e);
    int row = __ldg(ei + e);
    int col = __ldg(ei + E + e);
    int seg = __popc(__ballot_sync(0xffffffffu, sbp[lane] <= t));
    float u = __ldg(x + col * 32 + lane);

    const float* Ap = g_A + seg * 1024 + lane;
    const float* Bp = g_B + seg * 1024 + lane;
    float acc = 0.0f, accB = 0.0f;
    #pragma unroll
    for (int i = 0; i < 32; i++) {
        float xi = __shfl_sync(0xffffffffu, u, i);
        acc  = fmaf(xi, Ap[i * 32], acc);
        accB = fmaf(xi, Bp[i * 32], accB);
    }
    atomicAdd(out + row * 32 + lane, fmaf(t, accB, acc));
}

// ---------------------------------------------------------------------------
// K5: angle branch pass 1 — scatter (count, sum_t) per (node, segment)
// ---------------------------------------------------------------------------
__global__ void k_angle1(const int* __restrict__ ai, const float* __restrict__ ang, int A) {
    __shared__ float sbp[32];
    if (threadIdx.x < 32) sbp[threadIdx.x] = g_bp_a[threadIdx.x];
    __syncthreads();
    int a = blockIdx.x * blockDim.x + threadIdx.x;
    if (a >= A) return;
    float t = __ldg(ang + a);
    int j = __ldg(ai + A + a);   // angle_index[1]
    int seg = 0;
    #pragma unroll
    for (int i = 0; i < 32; i++) seg += (sbp[i] <= t) ? 1 : 0;
    atomicAdd(&g_cnt[j * SEGS + seg], 1.0f);
    atomicAdd(&g_ts[j * SEGS + seg], t);
}

// ---------------------------------------------------------------------------
// K6: angle branch pass 2 — dense per-node expansion. Warp per node.
// ---------------------------------------------------------------------------
__global__ void k_angle2(float* __restrict__ out, int N) {
    int j = (blockIdx.x * blockDim.x + threadIdx.x) >> 5;
    int lane = threadIdx.x & 31;
    if (j >= N) return;
    float acc = out[j * 32 + lane];
    const float* cp = g_cnt + j * SEGS;
    const float* tp = g_ts + j * SEGS;
    for (int s = 0; s < SEGS; s++) {
        float c = cp[s];                    // uniform broadcast load
        if (c != 0.0f) {
            float ts = tp[s];
            acc += c * g_aA[s * 32 + lane] + ts * g_aB[s * 32 + lane];
        }
    }
    out[j * 32 + lane] = acc;
}

// ---------------------------------------------------------------------------
extern "C" void kernel_launch(void* const* d_in, const int* in_sizes, int n_in,
                              void* d_out, int out_size) {
    const float* x   = (const float*)d_in[0];
    const int*   ei  = (const int*)d_in[1];
    const float* ea  = (const float*)d_in[2];
    const int*   ai  = (const int*)d_in[3];
    const float* ang = (const float*)d_in[4];
    const float* eW1 = (const float*)d_in[5];
    const float* eb1 = (const float*)d_in[6];
    const float* eW2 = (const float*)d_in[7];
    const float* eb2 = (const float*)d_in[8];
    const float* aW1 = (const float*)d_in[9];
    const float* ab1 = (const float*)d_in[10];
    const float* aW2 = (const float*)d_in[11];
    const float* ab2 = (const float*)d_in[12];
    float* out = (float*)d_out;

    int N = in_sizes[0] / CH;
    int E = in_sizes[1] / 2;
    int A = in_sizes[3] / 3;

    k_pre1<<<1, 64>>>(eW1, eb1, aW1, ab1);
    k_pre2<<<SEGS + 1, 256>>>(eW1, eb1, eW2, eb2, aW1, ab1, aW2, ab2);
    k_init<<<(N * SEGS + 255) / 256, 256>>>(out, N);
    k_edge<<<(E * 32 + 255) / 256, 256>>>(x, ei, ea, out, E);
    k_angle1<<<(A + 255) / 256, 256>>>(ai, ang, A);
    k_angle2<<<(N * 32 + 255) / 256, 256>>>(out, N);
}